// round 7
// baseline (speedup 1.0000x reference)
#include <cuda_runtime.h>

#define FULLMASK 0xffffffffu
#define NMO_   40
#define ROWS_  16
#define CSTR   12     // floats per stored MO column (48 B), column-major smem
#define CPB    32     // configs per block (256 threads = 64 quads = 32 cfg x 2 spins)

// Quad-cooperative Slater determinants: 4 lanes per 8x8 matrix, 2 rows/lane.
// - pivot chosen via packed-key unsigned max (value|lane|row) over the quad
// - no row data ever moves; retired rows masked out of the search
// - permutation sign computed ONCE at the end via inversion count of the
//   recorded pivot slots (no per-step position tracking)
__global__ __launch_bounds__(256, 6)
void slater_det_kernel(const float* __restrict__ mo,
                       const int*   __restrict__ cup,
                       const int*   __restrict__ cdown,
                       float*       __restrict__ out,
                       int nconf)
{
    __shared__ float mo_sh[2 * NMO_ * CSTR];   // 960 floats, column-major
    __shared__ float sh_det[64];

    const int b  = blockIdx.y;
    const int c0 = blockIdx.x * CPB;
    const int t  = threadIdx.x;

    // Stage this walker's MO block (16 x 40) column-major:
    // mo_sh[(s*40+col)*12 + i] = mo[b, s*8+i, col]
    {
        const float* src = mo + (size_t)b * (ROWS_ * NMO_);
        #pragma unroll
        for (int idx = t; idx < ROWS_ * NMO_; idx += 256) {
            const int e   = idx / NMO_;
            const int col = idx % NMO_;
            mo_sh[((e >> 3) * NMO_ + col) * CSTR + (e & 7)] = src[idx];
        }
    }
    __syncthreads();

    const int quad = t >> 2;          // 0..63
    const int lq   = t & 3;           // lane in quad; my rows = 2lq, 2lq+1
    const int s    = quad >> 5;       // spin channel
    const int c    = c0 + (quad & (CPB - 1));

    // Column indices: every lane of the quad loads the same 32B (broadcast hit).
    const int* cw = ((s == 0) ? cup : cdown) + c * 8;
    const int4 ci0 = __ldg((const int4*)cw);
    const int4 ci1 = __ldg((const int4*)cw + 1);
    const int cols[8] = {ci0.x, ci0.y, ci0.z, ci0.w, ci1.x, ci1.y, ci1.z, ci1.w};

    // Gather my two rows: column j is contiguous in smem -> one LDS.64 each.
    float a0[8], a1[8];
    {
        const int base = s * NMO_ * CSTR + 2 * lq;
        #pragma unroll
        for (int j = 0; j < 8; ++j) {
            const float2 p = *reinterpret_cast<const float2*>(mo_sh + base + cols[j] * CSTR);
            a0[j] = p.x;
            a1[j] = p.y;
        }
    }

    // LU with partial pivoting across the quad.
    float det = 1.0f;
    unsigned m0 = 0xFFFFFFFFu, m1 = 0xFFFFFFFFu;  // row-available masks
    int s0 = 0, s1 = 0;                           // slot each of my rows was pivoted at
    const unsigned tag0 = (unsigned)(lq << 1);
    const unsigned tag1 = tag0 | 1u;

    #pragma unroll
    for (int k = 0; k < 8; ++k) {
        // Packed pivot key: |a| bits (top 29) | lane (2) | row (1); retired rows -> 0.
        unsigned k0 = ((__float_as_uint(a0[k]) & 0x7FFFFFF8u) | tag0) & m0;
        unsigned k1 = ((__float_as_uint(a1[k]) & 0x7FFFFFF8u) | tag1) & m1;
        unsigned key = (k0 > k1) ? k0 : k1;
        {
            unsigned o = __shfl_xor_sync(FULLMASK, key, 1, 4);
            key = (o > key) ? o : key;
            o = __shfl_xor_sync(FULLMASK, key, 2, 4);
            key = (o > key) ? o : key;
        }
        const int wl = (int)((key >> 1) & 3u);    // winning lane in quad
        const int wr = (int)(key & 1u);           // winning row on that lane

        const float cand = wr ? a1[k] : a0[k];
        const float prk  = __shfl_sync(FULLMASK, cand, wl, 4);
        det *= prk;

        // Retire the pivot row; record its slot for the final sign.
        const bool meWin = (lq == wl);
        const bool g0 = meWin && (wr == 0);
        const bool g1 = meWin && (wr == 1);
        s0 = g0 ? k : s0;   m0 = g0 ? 0u : m0;
        s1 = g1 ? k : s1;   m1 = g1 ? 0u : m1;

        // Unconditional elimination on ALL rows: the pivot/retired rows get
        // corrupted but their keys are masked, so they are never read again.
        const float inv = __frcp_rn(prk);
        const float f0 = a0[k] * inv;
        const float f1 = a1[k] * inv;
        #pragma unroll
        for (int j = k + 1; j < 8; ++j) {
            const float cj  = wr ? a1[j] : a0[j];
            const float prj = __shfl_sync(FULLMASK, cj, wl, 4);
            a0[j] = fmaf(-f0, prj, a0[j]);
            a1[j] = fmaf(-f1, prj, a1[j]);
        }
    }

    // Permutation sign: inversions of (row -> pivot slot), counted once.
    {
        const int mypack = s0 | (s1 << 3);
        int cnt = (s0 > s1) ? 1 : 0;
        #pragma unroll
        for (int d = 1; d < 4; ++d) {
            const int other = __shfl_sync(FULLMASK, mypack, (lq + d) & 3, 4);
            if (lq + d < 4) {               // my rows are globally lower-indexed
                const int o0 = other & 7, o1 = other >> 3;
                cnt += (s0 > o0) + (s0 > o1) + (s1 > o0) + (s1 > o1);
            }
        }
        cnt += __shfl_xor_sync(FULLMASK, cnt, 1, 4);
        cnt += __shfl_xor_sync(FULLMASK, cnt, 2, 4);
        det = (cnt & 1) ? -det : det;
    }

    if (lq == 0) sh_det[quad] = det;
    __syncthreads();

    // Combine spins; coalesced 128B store per block.
    if (t < CPB)
        out[(size_t)b * nconf + c0 + t] = sh_det[t] * sh_det[CPB + t];
}

extern "C" void kernel_launch(void* const* d_in, const int* in_sizes, int n_in,
                              void* d_out, int out_size)
{
    const float* mo    = (const float*)d_in[0];  // (B, 16, 40) f32
    const int*   cup   = (const int*)  d_in[1];  // (C, 8) i32
    const int*   cdown = (const int*)  d_in[2];  // (C, 8) i32
    float*       out   = (float*)d_out;          // (B, C) f32

    const int B = in_sizes[0] / (ROWS_ * NMO_);
    const int C = in_sizes[1] / 8;

    dim3 grid(C / CPB, B);
    slater_det_kernel<<<grid, 256>>>(mo, cup, cdown, out, C);
}

// round 8
// speedup vs baseline: 1.2078x; 1.2078x over previous
#include <cuda_runtime.h>

#define FULLMASK 0xffffffffu
#define NMO_   40
#define ROWS_  16
#define CSTR   12     // floats per stored MO column; column-major smem
#define CPB    64     // configs per block (256 thr = 128 pairs = 64 cfg x 2 spins)

// 4-way register select via FSEL tree (no dynamic reg indexing).
__device__ __forceinline__ float sel4f(float x0, float x1, float x2, float x3, int r) {
    float lo = (r & 1) ? x1 : x0;
    float hi = (r & 1) ? x3 : x2;
    return (r & 2) ? hi : lo;
}

// Pair-cooperative Slater determinants: 2 lanes per 8x8 matrix, 4 rows/lane.
// Register-dieted so 5 CTAs/SM fit: sign via end-of-loop inversion count of
// packed pivot slots (no per-step position tracking), staged index loads,
// vectorized LDS.128 gather from column-major smem.
__global__ __launch_bounds__(256, 5)
void slater_det_kernel(const float* __restrict__ mo,
                       const int*   __restrict__ cup,
                       const int*   __restrict__ cdown,
                       float*       __restrict__ out,
                       int nconf)
{
    __shared__ __align__(16) float mo_sh[2 * NMO_ * CSTR];  // 960 floats
    __shared__ float sh_det[2 * CPB];

    const int b  = blockIdx.y;
    const int c0 = blockIdx.x * CPB;
    const int t  = threadIdx.x;

    // Stage column-major: mo_sh[(s*40+col)*12 + row8] = mo[b, s*8+row8, col]
    {
        const float* src = mo + (size_t)b * (ROWS_ * NMO_);
        #pragma unroll
        for (int idx = t; idx < ROWS_ * NMO_; idx += 256) {
            const int e   = idx / NMO_;
            const int col = idx % NMO_;
            mo_sh[((e >> 3) * NMO_ + col) * CSTR + (e & 7)] = src[idx];
        }
    }
    __syncthreads();

    const int pairid = t >> 1;            // 0..127
    const int par    = t & 1;             // lane in pair; my rows = par*4 + r
    const int s      = pairid >> 6;       // spin channel
    const int c      = c0 + (pairid & (CPB - 1));

    const int*   cw   = ((s == 0) ? cup : cdown) + c * 8;
    const float* base = mo_sh + s * NMO_ * CSTR + par * 4;  // 16B-aligned

    // Gather: each smem column holds 8 contiguous rows; my 4 rows = one LDS.128.
    // Index int4s staged one at a time to keep peak register pressure down.
    float a[4][8];
    {
        int4 ci = __ldg((const int4*)cw);
        const int c4[4] = {ci.x, ci.y, ci.z, ci.w};
        #pragma unroll
        for (int j = 0; j < 4; ++j) {
            const float4 p = *reinterpret_cast<const float4*>(base + c4[j] * CSTR);
            a[0][j] = p.x; a[1][j] = p.y; a[2][j] = p.z; a[3][j] = p.w;
        }
        ci = __ldg((const int4*)cw + 1);
        const int c8[4] = {ci.x, ci.y, ci.z, ci.w};
        #pragma unroll
        for (int j = 0; j < 4; ++j) {
            const float4 p = *reinterpret_cast<const float4*>(base + c8[j] * CSTR);
            a[0][4 + j] = p.x; a[1][4 + j] = p.y; a[2][4 + j] = p.z; a[3][4 + j] = p.w;
        }
    }

    // LU with partial pivoting across the lane pair.
    unsigned m0 = ~0u, m1 = ~0u, m2 = ~0u, m3 = ~0u;  // row-active masks
    int   spack = 0;                                  // 3-bit pivot slot per row
    float det   = 1.0f;
    const unsigned tagp = (unsigned)par;

    #pragma unroll
    for (int k = 0; k < 8; ++k) {
        // Packed key: |a| (top 29 bits, sign cleared) | row(2) | par(1);
        // retired rows masked to 0. Unsigned max => pivot value + location.
        unsigned k0 = ((__float_as_uint(a[0][k]) & 0x7FFFFFF8u) | 0u | tagp) & m0;
        unsigned k1 = ((__float_as_uint(a[1][k]) & 0x7FFFFFF8u) | 2u | tagp) & m1;
        unsigned k2 = ((__float_as_uint(a[2][k]) & 0x7FFFFFF8u) | 4u | tagp) & m2;
        unsigned k3 = ((__float_as_uint(a[3][k]) & 0x7FFFFFF8u) | 6u | tagp) & m3;
        unsigned key = (k0 > k1) ? k0 : k1;
        key = (k2 > key) ? k2 : key;
        key = (k3 > key) ? k3 : key;
        {
            const unsigned o = __shfl_xor_sync(FULLMASK, key, 1, 2);
            key = (o > key) ? o : key;
        }
        const int wpar   = (int)(key & 1u);
        const int r_star = (int)((key >> 1) & 3u);

        const float cand = sel4f(a[0][k], a[1][k], a[2][k], a[3][k], r_star);
        const float prk  = __shfl_sync(FULLMASK, cand, wpar, 2);
        det *= prk;

        // Retire pivot row; record its slot (for the final permutation sign).
        const bool meWin = (par == wpar);
        m0 = (meWin && r_star == 0) ? 0u : m0;
        m1 = (meWin && r_star == 1) ? 0u : m1;
        m2 = (meWin && r_star == 2) ? 0u : m2;
        m3 = (meWin && r_star == 3) ? 0u : m3;
        spack |= (meWin ? k : 0) << (3 * r_star);

        // Unconditional elimination on ALL rows: retired rows get corrupted
        // but their keys are masked, so they are never read again.
        const float inv = __frcp_rn(prk);
        const float f0 = a[0][k] * inv;
        const float f1 = a[1][k] * inv;
        const float f2 = a[2][k] * inv;
        const float f3 = a[3][k] * inv;
        #pragma unroll
        for (int j = k + 1; j < 8; ++j) {
            const float cj  = sel4f(a[0][j], a[1][j], a[2][j], a[3][j], r_star);
            const float prj = __shfl_sync(FULLMASK, cj, wpar, 2);
            a[0][j] = fmaf(-f0, prj, a[0][j]);
            a[1][j] = fmaf(-f1, prj, a[1][j]);
            a[2][j] = fmaf(-f2, prj, a[2][j]);
            a[3][j] = fmaf(-f3, prj, a[3][j]);
        }
    }

    // Permutation sign once: inversions of (global row -> pivot slot).
    {
        const int so = __shfl_xor_sync(FULLMASK, spack, 1, 2);
        const int s0 = spack & 7, s1 = (spack >> 3) & 7,
                  s2 = (spack >> 6) & 7, s3 = (spack >> 9) & 7;
        int cnt = (s0 > s1) + (s0 > s2) + (s0 > s3)
                + (s1 > s2) + (s1 > s3) + (s2 > s3);
        if (par == 0) {  // my rows (0-3) are globally below the partner's (4-7)
            const int o0 = so & 7, o1 = (so >> 3) & 7,
                      o2 = (so >> 6) & 7, o3 = (so >> 9) & 7;
            cnt += (s0 > o0) + (s0 > o1) + (s0 > o2) + (s0 > o3)
                 + (s1 > o0) + (s1 > o1) + (s1 > o2) + (s1 > o3)
                 + (s2 > o0) + (s2 > o1) + (s2 > o2) + (s2 > o3)
                 + (s3 > o0) + (s3 > o1) + (s3 > o2) + (s3 > o3);
        }
        cnt += __shfl_xor_sync(FULLMASK, cnt, 1, 2);
        det = (cnt & 1) ? -det : det;
    }

    if (par == 0) sh_det[pairid] = det;
    __syncthreads();

    // Combine spins; coalesced 256B store per block.
    if (t < CPB)
        out[(size_t)b * nconf + c0 + t] = sh_det[t] * sh_det[CPB + t];
}

extern "C" void kernel_launch(void* const* d_in, const int* in_sizes, int n_in,
                              void* d_out, int out_size)
{
    const float* mo    = (const float*)d_in[0];  // (B, 16, 40) f32
    const int*   cup   = (const int*)  d_in[1];  // (C, 8) i32
    const int*   cdown = (const int*)  d_in[2];  // (C, 8) i32
    float*       out   = (float*)d_out;          // (B, C) f32

    const int B = in_sizes[0] / (ROWS_ * NMO_);
    const int C = in_sizes[1] / 8;

    dim3 grid(C / CPB, B);
    slater_det_kernel<<<grid, 256>>>(mo, cup, cdown, out, C);
}

// round 9
// speedup vs baseline: 1.3958x; 1.1556x over previous
#include <cuda_runtime.h>

#define FULLMASK 0xffffffffu
#define NMO_   40
#define ROWS_  16
#define CSTR   12     // floats per stored MO column; column-major smem
#define CPB    32     // configs per block (128 thr = 64 pairs = 32 cfg x 2 spins)
#define TPB    128

// 4-way register select via FSEL tree (no dynamic reg indexing).
__device__ __forceinline__ float sel4f(float x0, float x1, float x2, float x3, int r) {
    const float lo = (r & 1) ? x1 : x0;
    const float hi = (r & 1) ? x3 : x2;
    return (r & 2) ? hi : lo;
}

// Pair-cooperative Slater determinants: 2 lanes per 8x8 matrix, 4 rows/lane.
// Pivot machinery dieted:
//  - retired rows become EXACTLY zero (winner multiplier forced to 1.0 =>
//    fmaf(-1, x, x) == 0 bit-exact), so no retirement masks are needed:
//    a zero row's pivot key is just its 3 tag bits and can never win.
//  - permutation sign from inversion count of recorded key-locs; the
//    loc->row map is a bit-rotation (even permutation), so parity carries over.
__global__ __launch_bounds__(TPB, 10)
void slater_det_kernel(const float* __restrict__ mo,
                       const int*   __restrict__ cup,
                       const int*   __restrict__ cdown,
                       float*       __restrict__ out,
                       int nconf)
{
    __shared__ __align__(16) float mo_sh[2 * NMO_ * CSTR];  // 960 floats
    __shared__ float sh_det[2 * CPB];

    const int b  = blockIdx.y;
    const int c0 = blockIdx.x * CPB;
    const int t  = threadIdx.x;

    // Stage column-major: mo_sh[(s*40+col)*12 + row8] = mo[b, s*8+row8, col]
    {
        const float* src = mo + (size_t)b * (ROWS_ * NMO_);
        #pragma unroll
        for (int idx = t; idx < ROWS_ * NMO_; idx += TPB) {
            const int e   = idx / NMO_;
            const int col = idx % NMO_;
            mo_sh[((e >> 3) * NMO_ + col) * CSTR + (e & 7)] = src[idx];
        }
    }
    __syncthreads();

    const int pairid = t >> 1;            // 0..63
    const int par    = t & 1;             // lane in pair; my rows = par*4 + r
    const int s      = pairid >> 5;       // spin channel
    const int c      = c0 + (pairid & (CPB - 1));

    const int*   cw   = ((s == 0) ? cup : cdown) + c * 8;
    const float* base = mo_sh + s * NMO_ * CSTR + par * 4;  // 16B-aligned

    // Gather: smem column = 8 contiguous rows; my 4 rows = one LDS.128/column.
    float a[4][8];
    {
        int4 ci = __ldg((const int4*)cw);
        const int c4[4] = {ci.x, ci.y, ci.z, ci.w};
        #pragma unroll
        for (int j = 0; j < 4; ++j) {
            const float4 p = *reinterpret_cast<const float4*>(base + c4[j] * CSTR);
            a[0][j] = p.x; a[1][j] = p.y; a[2][j] = p.z; a[3][j] = p.w;
        }
        ci = __ldg((const int4*)cw + 1);
        const int c8[4] = {ci.x, ci.y, ci.z, ci.w};
        #pragma unroll
        for (int j = 0; j < 4; ++j) {
            const float4 p = *reinterpret_cast<const float4*>(base + c8[j] * CSTR);
            a[0][4 + j] = p.x; a[1][4 + j] = p.y; a[2][4 + j] = p.z; a[3][4 + j] = p.w;
        }
    }

    // Row tags: loc = (row<<1)|par, distinct across the 8 global rows.
    const int l0 = par, l1 = par | 2, l2 = par | 4, l3 = par | 6;

    int   gp  = 0;       // packed winner locs, 3 bits per step (static shifts)
    float det = 1.0f;

    #pragma unroll
    for (int k = 0; k < 8; ++k) {
        // Key: |a| with low-3 mantissa bits replaced by the tag.
        // Retired rows are exactly 0 -> key = tag only -> never beats live rows.
        const unsigned k0 = (__float_as_uint(a[0][k]) & 0x7FFFFFF8u) | (unsigned)l0;
        const unsigned k1 = (__float_as_uint(a[1][k]) & 0x7FFFFFF8u) | (unsigned)l1;
        const unsigned k2 = (__float_as_uint(a[2][k]) & 0x7FFFFFF8u) | (unsigned)l2;
        const unsigned k3 = (__float_as_uint(a[3][k]) & 0x7FFFFFF8u) | (unsigned)l3;
        unsigned key = (k0 > k1) ? k0 : k1;
        key = (k2 > key) ? k2 : key;
        key = (k3 > key) ? k3 : key;
        {
            const unsigned o = __shfl_xor_sync(FULLMASK, key, 1, 2);
            key = (o > key) ? o : key;
        }
        const int loc    = (int)(key & 7u);
        const int wpar   = loc & 1;
        const int r_star = loc >> 1;

        gp += loc << (3 * k);   // record winner (disjoint bit ranges)

        const float cand = sel4f(a[0][k], a[1][k], a[2][k], a[3][k], r_star);
        const float prk  = __shfl_sync(FULLMASK, cand, wpar, 2);
        det *= prk;

        // Multipliers; the winner's is forced to exactly 1.0 so its row
        // self-annihilates bit-exactly (prj is its own value), staying 0
        // for all later steps (f = 0*inv = 0 afterwards).
        const float inv = __frcp_rn(prk);
        const float f0 = (loc == l0) ? 1.0f : a[0][k] * inv;
        const float f1 = (loc == l1) ? 1.0f : a[1][k] * inv;
        const float f2 = (loc == l2) ? 1.0f : a[2][k] * inv;
        const float f3 = (loc == l3) ? 1.0f : a[3][k] * inv;

        #pragma unroll
        for (int j = k + 1; j < 8; ++j) {
            const float cj  = sel4f(a[0][j], a[1][j], a[2][j], a[3][j], r_star);
            const float prj = __shfl_sync(FULLMASK, cj, wpar, 2);
            a[0][j] = fmaf(-f0, prj, a[0][j]);
            a[1][j] = fmaf(-f1, prj, a[1][j]);
            a[2][j] = fmaf(-f2, prj, a[2][j]);
            a[3][j] = fmaf(-f3, prj, a[3][j]);
        }
    }

    // Permutation parity from the loc sequence. loc->globalrow is a 3-bit
    // rotation = product of two 3-cycles = even, so parity(sigma)=parity(tau).
    {
        int l[8];
        #pragma unroll
        for (int k = 0; k < 8; ++k) l[k] = (gp >> (3 * k)) & 7;
        int cnt = 0;
        #pragma unroll
        for (int i = 0; i < 8; ++i)
            #pragma unroll
            for (int j = i + 1; j < 8; ++j)
                cnt += (l[i] > l[j]);
        det = (cnt & 1) ? -det : det;
    }

    if (par == 0) sh_det[pairid] = det;
    __syncthreads();

    // Combine spins; coalesced 128B store per block.
    if (t < CPB)
        out[(size_t)b * nconf + c0 + t] = sh_det[t] * sh_det[CPB + t];
}

extern "C" void kernel_launch(void* const* d_in, const int* in_sizes, int n_in,
                              void* d_out, int out_size)
{
    const float* mo    = (const float*)d_in[0];  // (B, 16, 40) f32
    const int*   cup   = (const int*)  d_in[1];  // (C, 8) i32
    const int*   cdown = (const int*)  d_in[2];  // (C, 8) i32
    float*       out   = (float*)d_out;          // (B, C) f32

    const int B = in_sizes[0] / (ROWS_ * NMO_);
    const int C = in_sizes[1] / 8;

    dim3 grid(C / CPB, B);
    slater_det_kernel<<<grid, TPB>>>(mo, cup, cdown, out, C);
}